// round 1
// baseline (speedup 1.0000x reference)
#include <cuda_runtime.h>
#include <cuda_bf16.h>

// Problem constants
#define NB   128   // batch
#define CI   64    // c_in
#define CO   64    // c_out
#define CINT 16    // c_int
#define TT   128   // time
#define VV   25    // vertices
#define VP   26    // padded V (8B-aligned rows, conflict-free stride)

// Scratch (device globals -- allocation-free rule)
__device__ float d_xmean[NB * CI * VV];          // [n, ci, v]
__device__ float d_Adyn [NB * CO * VV * VV];     // [n, c, u, v]

// ---------------- f32x2 packed helpers (Blackwell FFMA2 via PTX) ----------------
__device__ __forceinline__ unsigned long long pk2(float x, float y) {
    unsigned long long r;
    asm("mov.b64 %0, {%1, %2};" : "=l"(r) : "f"(x), "f"(y));
    return r;
}
__device__ __forceinline__ void fma2(unsigned long long& d, unsigned long long a,
                                     unsigned long long b) {
    asm("fma.rn.f32x2 %0, %1, %2, %0;" : "+l"(d) : "l"(a), "l"(b));
}
__device__ __forceinline__ void add2(unsigned long long& d, unsigned long long a) {
    asm("add.rn.f32x2 %0, %0, %1;" : "+l"(d) : "l"(a));
}
__device__ __forceinline__ void unpk2(unsigned long long v, float& x, float& y) {
    asm("mov.b64 {%0, %1}, %2;" : "=f"(x), "=f"(y) : "l"(v));
}

// ---------------- K1: x_mean[n,ci,v] = mean_t x[n,ci,t,v] ----------------
__global__ void k_mean(const float* __restrict__ x) {
    int idx = blockIdx.x * blockDim.x + threadIdx.x;     // over NB*CI*VV = 204800
    if (idx >= NB * CI * VV) return;
    int v  = idx % VV;
    int nc = idx / VV;                                   // n*CI + ci
    const float* p = x + (size_t)nc * (TT * VV) + v;
    float s = 0.f;
#pragma unroll 8
    for (int t = 0; t < TT; t++) s += p[t * VV];
    d_xmean[idx] = s * (1.0f / (float)TT);
}

// ---------------- K2: A_dyn[n,c,u,v] ----------------
// theta[i,u]=bth+Wth.xm ; phi[i,v]=bph+Wph.xm ; rel=tanh(theta[u]-phi[v])
// A_dyn = (A+PA)[u,v] + alpha*(Wr.rel + br)
__global__ void k_adyn(const float* __restrict__ A,  const float* __restrict__ PA,
                       const float* __restrict__ alpha,
                       const float* __restrict__ Wth, const float* __restrict__ bth,
                       const float* __restrict__ Wph, const float* __restrict__ bph,
                       const float* __restrict__ Wr,  const float* __restrict__ br) {
    __shared__ float th[CINT * VV];        // 400
    __shared__ float ph[CINT * VV];        // 400
    __shared__ float relb[CINT * VV * VV]; // 10000 -> 40KB
    int n = blockIdx.x, tid = threadIdx.x;
    const float* xmn = d_xmean + n * (CI * VV);

    for (int idx = tid; idx < 2 * CINT * VV; idx += blockDim.x) {
        bool is_th = (idx < CINT * VV);
        int  base  = is_th ? idx : (idx - CINT * VV);
        int  i = base / VV, v = base % VV;
        const float* W = is_th ? Wth : Wph;
        float acc = is_th ? bth[i] : bph[i];
#pragma unroll 8
        for (int ci = 0; ci < CI; ci++)
            acc += W[i * CI + ci] * xmn[ci * VV + v];
        if (is_th) th[base] = acc; else ph[base] = acc;
    }
    __syncthreads();

    for (int idx = tid; idx < CINT * VV * VV; idx += blockDim.x) {
        int i = idx / (VV * VV), r = idx % (VV * VV);
        int u = r / VV, v = r % VV;
        relb[idx] = tanhf(th[i * VV + u] - ph[i * VV + v]);
    }
    __syncthreads();

    float al = alpha[0];
    float* Adn = d_Adyn + (size_t)n * (CO * VV * VV);
    for (int idx = tid; idx < CO * VV * VV; idx += blockDim.x) {
        int c = idx / (VV * VV), r = idx % (VV * VV);
        float s = br[c];
#pragma unroll
        for (int i = 0; i < CINT; i++)
            s += Wr[c * CINT + i] * relb[i * (VV * VV) + r];
        Adn[idx] = A[r] + PA[r] + al * s;
    }
}

// ---------------- K3: fused g + graph aggregation ----------------
// out[n,c,t,u] = sum_v (sum_ci Wg[c,ci] x[n,ci,t,v] + bg[c]) * A_dyn[n,c,u,v]
// Block: one (n, 16-t tile). Two chunks of 32 c. Each thread: 2 c's x 1 t.
#define TTILE 16
#define CCH   32
// smem float offsets
#define OFF_XS   0                                  // [CI][TTILE][VP]  = 26624
#define OFF_WG   (CI * TTILE * VP)                  // [CO][CI]         = 4096
#define OFF_ADS  (OFF_WG + CO * CI)                 // [CCH][VV][VP]    = 20800
#define OFF_BG   (OFF_ADS + CCH * VV * VP)          // [CO]
#define SMEM_FLOATS (OFF_BG + CO)
#define SMEM_BYTES  (SMEM_FLOATS * 4)               // 206,592 B

__global__ void __launch_bounds__(256, 1)
k_main(const float* __restrict__ x, const float* __restrict__ Wg,
       const float* __restrict__ bg, float* __restrict__ out) {
    extern __shared__ float sm[];
    float* xs  = sm + OFF_XS;
    float* Wgs = sm + OFF_WG;
    float* Ads = sm + OFF_ADS;
    float* bgs = sm + OFF_BG;

    int n   = blockIdx.x;
    int t0  = blockIdx.y * TTILE;
    int tid = threadIdx.x;

    // Stage weights + bias
    for (int i = tid; i < CO * CI; i += 256) Wgs[i] = Wg[i];
    if (tid < CO) bgs[tid] = bg[tid];

    // Stage x tile: x[n, ci, t0..t0+15, 0..24] -> xs[ci][t][v] (VP-padded)
    const float* xb = x + ((size_t)n * CI) * (TT * VV) + (size_t)t0 * VV;
    for (int i = tid; i < CI * TTILE * VV; i += 256) {
        int ci = i / (TTILE * VV), r = i % (TTILE * VV);
        int t = r / VV, v = r % VV;
        xs[(ci * TTILE + t) * VP + v] = xb[(size_t)ci * (TT * VV) + r];
    }
    for (int i = tid; i < CI * TTILE; i += 256) xs[i * VP + VV] = 0.f;  // zero pad

    int cg = tid >> 4;      // 0..15 -> c-pair index within chunk
    int t  = tid & 15;      // 0..15 -> t within tile

    for (int cc = 0; cc < 2; cc++) {
        __syncthreads();    // xs ready (iter0) / previous chunk compute done (iter1)

        // Stage A_dyn chunk: 32 c's
        const float* Adb = d_Adyn + ((size_t)n * CO + cc * CCH) * (VV * VV);
        for (int i = tid; i < CCH * VV * VV; i += 256) {
            int c = i / (VV * VV), r = i % (VV * VV);
            int u = r / VV, v = r % VV;
            Ads[(c * VV + u) * VP + v] = Adb[i];
        }
        for (int i = tid; i < CCH * VV; i += 256) Ads[i * VP + VV] = 0.f;  // zero pad
        __syncthreads();

        int c0    = cg * 2;            // local c in chunk (c0, c0+1)
        int cglob = cc * CCH + c0;

        // --- g accumulation in packed f32x2: g[c, v-pairs] ---
        unsigned long long ga[13], gb[13];
#pragma unroll
        for (int j = 0; j < 13; j++) { ga[j] = 0ull; gb[j] = 0ull; }

#pragma unroll 4
        for (int ci = 0; ci < CI; ci++) {
            float wa = Wgs[cglob * CI + ci];
            float wb = Wgs[(cglob + 1) * CI + ci];
            unsigned long long wa2 = pk2(wa, wa);
            unsigned long long wb2 = pk2(wb, wb);
            const unsigned long long* xv =
                reinterpret_cast<const unsigned long long*>(xs + (ci * TTILE + t) * VP);
#pragma unroll
            for (int j = 0; j < 13; j++) {
                unsigned long long xj = xv[j];
                fma2(ga[j], wa2, xj);
                fma2(gb[j], wb2, xj);
            }
        }
        {   // bias (pad lane harmless: Ads pad column is zero)
            unsigned long long ba2 = pk2(bgs[cglob], bgs[cglob]);
            unsigned long long bb2 = pk2(bgs[cglob + 1], bgs[cglob + 1]);
#pragma unroll
            for (int j = 0; j < 13; j++) { add2(ga[j], ba2); add2(gb[j], bb2); }
        }

        // --- contraction with A_dyn ---
        float* ob = out + (((size_t)n * CO + cglob) * TT + (t0 + t)) * VV;
#pragma unroll 1
        for (int u = 0; u < VV; u++) {
            const unsigned long long* ava =
                reinterpret_cast<const unsigned long long*>(Ads + (c0 * VV + u) * VP);
            const unsigned long long* avb =
                reinterpret_cast<const unsigned long long*>(Ads + ((c0 + 1) * VV + u) * VP);
            unsigned long long acca = 0ull, accb = 0ull;
#pragma unroll
            for (int j = 0; j < 13; j++) {
                fma2(acca, ga[j], ava[j]);
                fma2(accb, gb[j], avb[j]);
            }
            float ax, ay, bx, by;
            unpk2(acca, ax, ay);
            unpk2(accb, bx, by);
            ob[u]           = ax + ay;
            ob[TT * VV + u] = bx + by;   // next c
        }
    }
}

// ---------------- launcher ----------------
extern "C" void kernel_launch(void* const* d_in, const int* in_sizes, int n_in,
                              void* d_out, int out_size) {
    const float* x     = (const float*)d_in[0];
    const float* A     = (const float*)d_in[1];
    const float* PA    = (const float*)d_in[2];
    const float* alpha = (const float*)d_in[3];
    const float* Wg    = (const float*)d_in[4];
    const float* bg    = (const float*)d_in[5];
    const float* Wth   = (const float*)d_in[6];
    const float* bth   = (const float*)d_in[7];
    const float* Wph   = (const float*)d_in[8];
    const float* bph   = (const float*)d_in[9];
    const float* Wr    = (const float*)d_in[10];
    const float* br    = (const float*)d_in[11];
    float* out = (float*)d_out;
    (void)in_sizes; (void)n_in; (void)out_size;

    cudaFuncSetAttribute(k_main, cudaFuncAttributeMaxDynamicSharedMemorySize,
                         SMEM_BYTES);

    k_mean<<<(NB * CI * VV + 255) / 256, 256>>>(x);
    k_adyn<<<NB, 256>>>(A, PA, alpha, Wth, bth, Wph, bph, Wr, br);
    k_main<<<dim3(NB, TT / TTILE), 256, SMEM_BYTES>>>(x, Wg, bg, out);
}

// round 2
// speedup vs baseline: 1.0088x; 1.0088x over previous
#include <cuda_runtime.h>
#include <cuda_bf16.h>

// Problem constants
#define NB   128   // batch
#define CI   64    // c_in
#define CO   64    // c_out
#define CINT 16    // c_int
#define TT   128   // time
#define VV   25    // vertices
#define VP   26    // padded V (8B-aligned rows, conflict-free stride)

// Scratch (device globals -- allocation-free rule)
__device__ float d_xmean[NB * CI * VV];          // [n, ci, v]
__device__ float d_Adyn [NB * CO * VV * VV];     // [n, c, u, v]

// ---------------- f32x2 packed helpers (Blackwell FFMA2 via PTX) ----------------
__device__ __forceinline__ unsigned long long pk2(float x, float y) {
    unsigned long long r;
    asm("mov.b64 %0, {%1, %2};" : "=l"(r) : "f"(x), "f"(y));
    return r;
}
__device__ __forceinline__ void fma2(unsigned long long& d, unsigned long long a,
                                     unsigned long long b) {
    asm("fma.rn.f32x2 %0, %1, %2, %0;" : "+l"(d) : "l"(a), "l"(b));
}
__device__ __forceinline__ void add2(unsigned long long& d, unsigned long long a) {
    asm("add.rn.f32x2 %0, %0, %1;" : "+l"(d) : "l"(a));
}
__device__ __forceinline__ void unpk2(unsigned long long v, float& x, float& y) {
    asm("mov.b64 {%0, %1}, %2;" : "=f"(x), "=f"(y) : "l"(v));
}

// ---------------- K1: x_mean[n,ci,v] = mean_t x[n,ci,t,v] ----------------
__global__ void k_mean(const float* __restrict__ x) {
    int idx = blockIdx.x * blockDim.x + threadIdx.x;     // over NB*CI*VV = 204800
    if (idx >= NB * CI * VV) return;
    int v  = idx % VV;
    int nc = idx / VV;                                   // n*CI + ci
    const float* p = x + (size_t)nc * (TT * VV) + v;
    float s = 0.f;
#pragma unroll 8
    for (int t = 0; t < TT; t++) s += p[t * VV];
    d_xmean[idx] = s * (1.0f / (float)TT);
}

// ---------------- K2: A_dyn[n,c,u,v] ----------------
// theta[i,u]=bth+Wth.xm ; phi[i,v]=bph+Wph.xm ; rel=tanh(theta[u]-phi[v])
// A_dyn = (A+PA)[u,v] + alpha*(Wr.rel + br)
__global__ void k_adyn(const float* __restrict__ A,  const float* __restrict__ PA,
                       const float* __restrict__ alpha,
                       const float* __restrict__ Wth, const float* __restrict__ bth,
                       const float* __restrict__ Wph, const float* __restrict__ bph,
                       const float* __restrict__ Wr,  const float* __restrict__ br) {
    __shared__ float th[CINT * VV];        // 400
    __shared__ float ph[CINT * VV];        // 400
    __shared__ float relb[CINT * VV * VV]; // 10000 -> 40KB
    int n = blockIdx.x, tid = threadIdx.x;
    const float* xmn = d_xmean + n * (CI * VV);

    for (int idx = tid; idx < 2 * CINT * VV; idx += blockDim.x) {
        bool is_th = (idx < CINT * VV);
        int  base  = is_th ? idx : (idx - CINT * VV);
        int  i = base / VV, v = base % VV;
        const float* W = is_th ? Wth : Wph;
        float acc = is_th ? bth[i] : bph[i];
#pragma unroll 8
        for (int ci = 0; ci < CI; ci++)
            acc += W[i * CI + ci] * xmn[ci * VV + v];
        if (is_th) th[base] = acc; else ph[base] = acc;
    }
    __syncthreads();

    for (int idx = tid; idx < CINT * VV * VV; idx += blockDim.x) {
        int i = idx / (VV * VV), r = idx % (VV * VV);
        int u = r / VV, v = r % VV;
        relb[idx] = tanhf(th[i * VV + u] - ph[i * VV + v]);
    }
    __syncthreads();

    float al = alpha[0];
    float* Adn = d_Adyn + (size_t)n * (CO * VV * VV);
    for (int idx = tid; idx < CO * VV * VV; idx += blockDim.x) {
        int c = idx / (VV * VV), r = idx % (VV * VV);
        float s = br[c];
#pragma unroll
        for (int i = 0; i < CINT; i++)
            s += Wr[c * CINT + i] * relb[i * (VV * VV) + r];
        Adn[idx] = A[r] + PA[r] + al * s;
    }
}

// ---------------- K3: fused g + graph aggregation ----------------
// out[n,c,t,u] = sum_v (sum_ci Wg[c,ci] x[n,ci,t,v] + bg[c]) * A_dyn[n,c,u,v]
// Block: one (n, 16-t tile). Two chunks of 32 c. Each thread: 2 c's x 1 t.
#define TTILE 16
#define CCH   32
// smem float offsets
#define OFF_XS   0                                  // [CI][TTILE][VP]  = 26624
#define OFF_WG   (CI * TTILE * VP)                  // [CO][CI]         = 4096
#define OFF_ADS  (OFF_WG + CO * CI)                 // [CCH][VV][VP]    = 20800
#define OFF_BG   (OFF_ADS + CCH * VV * VP)          // [CO]
#define SMEM_FLOATS (OFF_BG + CO)
#define SMEM_BYTES  (SMEM_FLOATS * 4)               // 206,592 B

__global__ void __launch_bounds__(256, 1)
k_main(const float* __restrict__ x, const float* __restrict__ Wg,
       const float* __restrict__ bg, float* __restrict__ out) {
    extern __shared__ float sm[];
    float* xs  = sm + OFF_XS;
    float* Wgs = sm + OFF_WG;
    float* Ads = sm + OFF_ADS;
    float* bgs = sm + OFF_BG;

    int n   = blockIdx.x;
    int t0  = blockIdx.y * TTILE;
    int tid = threadIdx.x;

    // Stage weights + bias
    for (int i = tid; i < CO * CI; i += 256) Wgs[i] = Wg[i];
    if (tid < CO) bgs[tid] = bg[tid];

    // Stage x tile: x[n, ci, t0..t0+15, 0..24] -> xs[ci][t][v] (VP-padded)
    const float* xb = x + ((size_t)n * CI) * (TT * VV) + (size_t)t0 * VV;
    for (int i = tid; i < CI * TTILE * VV; i += 256) {
        int ci = i / (TTILE * VV), r = i % (TTILE * VV);
        int t = r / VV, v = r % VV;
        xs[(ci * TTILE + t) * VP + v] = xb[(size_t)ci * (TT * VV) + r];
    }
    for (int i = tid; i < CI * TTILE; i += 256) xs[i * VP + VV] = 0.f;  // zero pad

    int cg = tid >> 4;      // 0..15 -> c-pair index within chunk
    int t  = tid & 15;      // 0..15 -> t within tile

    for (int cc = 0; cc < 2; cc++) {
        __syncthreads();    // xs ready (iter0) / previous chunk compute done (iter1)

        // Stage A_dyn chunk: 32 c's
        const float* Adb = d_Adyn + ((size_t)n * CO + cc * CCH) * (VV * VV);
        for (int i = tid; i < CCH * VV * VV; i += 256) {
            int c = i / (VV * VV), r = i % (VV * VV);
            int u = r / VV, v = r % VV;
            Ads[(c * VV + u) * VP + v] = Adb[i];
        }
        for (int i = tid; i < CCH * VV; i += 256) Ads[i * VP + VV] = 0.f;  // zero pad
        __syncthreads();

        int c0    = cg * 2;            // local c in chunk (c0, c0+1)
        int cglob = cc * CCH + c0;

        // --- g accumulation in packed f32x2: g[c, v-pairs] ---
        unsigned long long ga[13], gb[13];
#pragma unroll
        for (int j = 0; j < 13; j++) { ga[j] = 0ull; gb[j] = 0ull; }

#pragma unroll 4
        for (int ci = 0; ci < CI; ci++) {
            float wa = Wgs[cglob * CI + ci];
            float wb = Wgs[(cglob + 1) * CI + ci];
            unsigned long long wa2 = pk2(wa, wa);
            unsigned long long wb2 = pk2(wb, wb);
            const unsigned long long* xv =
                reinterpret_cast<const unsigned long long*>(xs + (ci * TTILE + t) * VP);
#pragma unroll
            for (int j = 0; j < 13; j++) {
                unsigned long long xj = xv[j];
                fma2(ga[j], wa2, xj);
                fma2(gb[j], wb2, xj);
            }
        }
        {   // bias (pad lane harmless: Ads pad column is zero)
            unsigned long long ba2 = pk2(bgs[cglob], bgs[cglob]);
            unsigned long long bb2 = pk2(bgs[cglob + 1], bgs[cglob + 1]);
#pragma unroll
            for (int j = 0; j < 13; j++) { add2(ga[j], ba2); add2(gb[j], bb2); }
        }

        // --- contraction with A_dyn ---
        float* ob = out + (((size_t)n * CO + cglob) * TT + (t0 + t)) * VV;
#pragma unroll 1
        for (int u = 0; u < VV; u++) {
            const unsigned long long* ava =
                reinterpret_cast<const unsigned long long*>(Ads + (c0 * VV + u) * VP);
            const unsigned long long* avb =
                reinterpret_cast<const unsigned long long*>(Ads + ((c0 + 1) * VV + u) * VP);
            unsigned long long acca = 0ull, accb = 0ull;
#pragma unroll
            for (int j = 0; j < 13; j++) {
                fma2(acca, ga[j], ava[j]);
                fma2(accb, gb[j], avb[j]);
            }
            float ax, ay, bx, by;
            unpk2(acca, ax, ay);
            unpk2(accb, bx, by);
            ob[u]           = ax + ay;
            ob[TT * VV + u] = bx + by;   // next c
        }
    }
}

// ---------------- launcher ----------------
extern "C" void kernel_launch(void* const* d_in, const int* in_sizes, int n_in,
                              void* d_out, int out_size) {
    const float* x     = (const float*)d_in[0];
    const float* A     = (const float*)d_in[1];
    const float* PA    = (const float*)d_in[2];
    const float* alpha = (const float*)d_in[3];
    const float* Wg    = (const float*)d_in[4];
    const float* bg    = (const float*)d_in[5];
    const float* Wth   = (const float*)d_in[6];
    const float* bth   = (const float*)d_in[7];
    const float* Wph   = (const float*)d_in[8];
    const float* bph   = (const float*)d_in[9];
    const float* Wr    = (const float*)d_in[10];
    const float* br    = (const float*)d_in[11];
    float* out = (float*)d_out;
    (void)in_sizes; (void)n_in; (void)out_size;

    cudaFuncSetAttribute(k_main, cudaFuncAttributeMaxDynamicSharedMemorySize,
                         SMEM_BYTES);

    k_mean<<<(NB * CI * VV + 255) / 256, 256>>>(x);
    k_adyn<<<NB, 256>>>(A, PA, alpha, Wth, bth, Wph, bph, Wr, br);
    k_main<<<dim3(NB, TT / TTILE), 256, SMEM_BYTES>>>(x, Wg, bg, out);
}

// round 3
// speedup vs baseline: 1.0101x; 1.0013x over previous
#include <cuda_runtime.h>
#include <cuda_bf16.h>

// Problem constants
#define NB   128   // batch
#define CI   64    // c_in
#define CO   64    // c_out
#define CINT 16    // c_int
#define TT   128   // time
#define VV   25    // vertices
#define VP   26    // padded V (8B-aligned rows, conflict-free stride)

// Scratch (device globals -- allocation-free rule)
__device__ float d_xmean[NB * CI * VV];          // [n, ci, v]
__device__ float d_Adyn [NB * CO * VV * VV];     // [n, c, u, v]

// ---------------- f32x2 packed helpers (Blackwell FFMA2 via PTX) ----------------
__device__ __forceinline__ unsigned long long pk2(float x, float y) {
    unsigned long long r;
    asm("mov.b64 %0, {%1, %2};" : "=l"(r) : "f"(x), "f"(y));
    return r;
}
__device__ __forceinline__ void fma2(unsigned long long& d, unsigned long long a,
                                     unsigned long long b) {
    asm("fma.rn.f32x2 %0, %1, %2, %0;" : "+l"(d) : "l"(a), "l"(b));
}
__device__ __forceinline__ void add2(unsigned long long& d, unsigned long long a) {
    asm("add.rn.f32x2 %0, %0, %1;" : "+l"(d) : "l"(a));
}
__device__ __forceinline__ void unpk2(unsigned long long v, float& x, float& y) {
    asm("mov.b64 {%0, %1}, %2;" : "=f"(x), "=f"(y) : "l"(v));
}

// ---------------- K1: x_mean[n,ci,v] = mean_t x[n,ci,t,v] ----------------
__global__ void k_mean(const float* __restrict__ x) {
    int idx = blockIdx.x * blockDim.x + threadIdx.x;     // over NB*CI*VV = 204800
    if (idx >= NB * CI * VV) return;
    int v  = idx % VV;
    int nc = idx / VV;                                   // n*CI + ci
    const float* p = x + (size_t)nc * (TT * VV) + v;
    float s = 0.f;
#pragma unroll 8
    for (int t = 0; t < TT; t++) s += p[t * VV];
    d_xmean[idx] = s * (1.0f / (float)TT);
}

// ---------------- K2: A_dyn[n,c,u,v] ----------------
// theta[i,u]=bth+Wth.xm ; phi[i,v]=bph+Wph.xm ; rel=tanh(theta[u]-phi[v])
// A_dyn = (A+PA)[u,v] + alpha*(Wr.rel + br)
__global__ void k_adyn(const float* __restrict__ A,  const float* __restrict__ PA,
                       const float* __restrict__ alpha,
                       const float* __restrict__ Wth, const float* __restrict__ bth,
                       const float* __restrict__ Wph, const float* __restrict__ bph,
                       const float* __restrict__ Wr,  const float* __restrict__ br) {
    __shared__ float th[CINT * VV];        // 400
    __shared__ float ph[CINT * VV];        // 400
    __shared__ float relb[CINT * VV * VV]; // 10000 -> 40KB
    int n = blockIdx.x, tid = threadIdx.x;
    const float* xmn = d_xmean + n * (CI * VV);

    for (int idx = tid; idx < 2 * CINT * VV; idx += blockDim.x) {
        bool is_th = (idx < CINT * VV);
        int  base  = is_th ? idx : (idx - CINT * VV);
        int  i = base / VV, v = base % VV;
        const float* W = is_th ? Wth : Wph;
        float acc = is_th ? bth[i] : bph[i];
#pragma unroll 8
        for (int ci = 0; ci < CI; ci++)
            acc += W[i * CI + ci] * xmn[ci * VV + v];
        if (is_th) th[base] = acc; else ph[base] = acc;
    }
    __syncthreads();

    for (int idx = tid; idx < CINT * VV * VV; idx += blockDim.x) {
        int i = idx / (VV * VV), r = idx % (VV * VV);
        int u = r / VV, v = r % VV;
        relb[idx] = tanhf(th[i * VV + u] - ph[i * VV + v]);
    }
    __syncthreads();

    float al = alpha[0];
    float* Adn = d_Adyn + (size_t)n * (CO * VV * VV);
    for (int idx = tid; idx < CO * VV * VV; idx += blockDim.x) {
        int c = idx / (VV * VV), r = idx % (VV * VV);
        float s = br[c];
#pragma unroll
        for (int i = 0; i < CINT; i++)
            s += Wr[c * CINT + i] * relb[i * (VV * VV) + r];
        Adn[idx] = A[r] + PA[r] + al * s;
    }
}

// ---------------- K3: fused g + graph aggregation ----------------
// out[n,c,t,u] = sum_v (sum_ci Wg[c,ci] x[n,ci,t,v] + bg[c]) * A_dyn[n,c,u,v]
// Block: one (n, 16-t tile). Two chunks of 32 c. Each thread: 2 c's x 1 t.
#define TTILE 16
#define CCH   32
// smem float offsets
#define OFF_XS   0                                  // [CI][TTILE][VP]  = 26624
#define OFF_WG   (CI * TTILE * VP)                  // [CO][CI]         = 4096
#define OFF_ADS  (OFF_WG + CO * CI)                 // [CCH][VV][VP]    = 20800
#define OFF_BG   (OFF_ADS + CCH * VV * VP)          // [CO]
#define SMEM_FLOATS (OFF_BG + CO)
#define SMEM_BYTES  (SMEM_FLOATS * 4)               // 206,592 B

__global__ void __launch_bounds__(256, 1)
k_main(const float* __restrict__ x, const float* __restrict__ Wg,
       const float* __restrict__ bg, float* __restrict__ out) {
    extern __shared__ float sm[];
    float* xs  = sm + OFF_XS;
    float* Wgs = sm + OFF_WG;
    float* Ads = sm + OFF_ADS;
    float* bgs = sm + OFF_BG;

    int n   = blockIdx.x;
    int t0  = blockIdx.y * TTILE;
    int tid = threadIdx.x;

    // Stage weights + bias
    for (int i = tid; i < CO * CI; i += 256) Wgs[i] = Wg[i];
    if (tid < CO) bgs[tid] = bg[tid];

    // Stage x tile: x[n, ci, t0..t0+15, 0..24] -> xs[ci][t][v] (VP-padded)
    const float* xb = x + ((size_t)n * CI) * (TT * VV) + (size_t)t0 * VV;
    for (int i = tid; i < CI * TTILE * VV; i += 256) {
        int ci = i / (TTILE * VV), r = i % (TTILE * VV);
        int t = r / VV, v = r % VV;
        xs[(ci * TTILE + t) * VP + v] = xb[(size_t)ci * (TT * VV) + r];
    }
    for (int i = tid; i < CI * TTILE; i += 256) xs[i * VP + VV] = 0.f;  // zero pad

    int cg = tid >> 4;      // 0..15 -> c-pair index within chunk
    int t  = tid & 15;      // 0..15 -> t within tile

    for (int cc = 0; cc < 2; cc++) {
        __syncthreads();    // xs ready (iter0) / previous chunk compute done (iter1)

        // Stage A_dyn chunk: 32 c's
        const float* Adb = d_Adyn + ((size_t)n * CO + cc * CCH) * (VV * VV);
        for (int i = tid; i < CCH * VV * VV; i += 256) {
            int c = i / (VV * VV), r = i % (VV * VV);
            int u = r / VV, v = r % VV;
            Ads[(c * VV + u) * VP + v] = Adb[i];
        }
        for (int i = tid; i < CCH * VV; i += 256) Ads[i * VP + VV] = 0.f;  // zero pad
        __syncthreads();

        int c0    = cg * 2;            // local c in chunk (c0, c0+1)
        int cglob = cc * CCH + c0;

        // --- g accumulation in packed f32x2: g[c, v-pairs] ---
        unsigned long long ga[13], gb[13];
#pragma unroll
        for (int j = 0; j < 13; j++) { ga[j] = 0ull; gb[j] = 0ull; }

#pragma unroll 4
        for (int ci = 0; ci < CI; ci++) {
            float wa = Wgs[cglob * CI + ci];
            float wb = Wgs[(cglob + 1) * CI + ci];
            unsigned long long wa2 = pk2(wa, wa);
            unsigned long long wb2 = pk2(wb, wb);
            const unsigned long long* xv =
                reinterpret_cast<const unsigned long long*>(xs + (ci * TTILE + t) * VP);
#pragma unroll
            for (int j = 0; j < 13; j++) {
                unsigned long long xj = xv[j];
                fma2(ga[j], wa2, xj);
                fma2(gb[j], wb2, xj);
            }
        }
        {   // bias (pad lane harmless: Ads pad column is zero)
            unsigned long long ba2 = pk2(bgs[cglob], bgs[cglob]);
            unsigned long long bb2 = pk2(bgs[cglob + 1], bgs[cglob + 1]);
#pragma unroll
            for (int j = 0; j < 13; j++) { add2(ga[j], ba2); add2(gb[j], bb2); }
        }

        // --- contraction with A_dyn ---
        float* ob = out + (((size_t)n * CO + cglob) * TT + (t0 + t)) * VV;
#pragma unroll 1
        for (int u = 0; u < VV; u++) {
            const unsigned long long* ava =
                reinterpret_cast<const unsigned long long*>(Ads + (c0 * VV + u) * VP);
            const unsigned long long* avb =
                reinterpret_cast<const unsigned long long*>(Ads + ((c0 + 1) * VV + u) * VP);
            unsigned long long acca = 0ull, accb = 0ull;
#pragma unroll
            for (int j = 0; j < 13; j++) {
                fma2(acca, ga[j], ava[j]);
                fma2(accb, gb[j], avb[j]);
            }
            float ax, ay, bx, by;
            unpk2(acca, ax, ay);
            unpk2(accb, bx, by);
            ob[u]           = ax + ay;
            ob[TT * VV + u] = bx + by;   // next c
        }
    }
}

// ---------------- launcher ----------------
extern "C" void kernel_launch(void* const* d_in, const int* in_sizes, int n_in,
                              void* d_out, int out_size) {
    const float* x     = (const float*)d_in[0];
    const float* A     = (const float*)d_in[1];
    const float* PA    = (const float*)d_in[2];
    const float* alpha = (const float*)d_in[3];
    const float* Wg    = (const float*)d_in[4];
    const float* bg    = (const float*)d_in[5];
    const float* Wth   = (const float*)d_in[6];
    const float* bth   = (const float*)d_in[7];
    const float* Wph   = (const float*)d_in[8];
    const float* bph   = (const float*)d_in[9];
    const float* Wr    = (const float*)d_in[10];
    const float* br    = (const float*)d_in[11];
    float* out = (float*)d_out;
    (void)in_sizes; (void)n_in; (void)out_size;

    cudaFuncSetAttribute(k_main, cudaFuncAttributeMaxDynamicSharedMemorySize,
                         SMEM_BYTES);

    k_mean<<<(NB * CI * VV + 255) / 256, 256>>>(x);
    k_adyn<<<NB, 256>>>(A, PA, alpha, Wth, bth, Wph, bph, Wr, br);
    k_main<<<dim3(NB, TT / TTILE), 256, SMEM_BYTES>>>(x, Wg, bg, out);
}